// round 7
// baseline (speedup 1.0000x reference)
#include <cuda_runtime.h>
#include <cuda_fp16.h>
#include <math.h>
#include <stdint.h>

#define N_NODES 50000
#define N_EDGES 800000
#define N_H 4
#define HC 128
#define NEG_SLOPE 0.2f
#define MAXDEG 96

#define BM 64
#define AS_STRIDE 132   // padded row stride (uint32) for A tile

// ---------------- scratch (device globals; no allocation) ----------------
__device__ __align__(16) __half g_xwh[N_NODES * HC];   // A @ W (fp16 features)
__device__ __align__(16) __half g_aggh[N_NODES * HC];  // elu(agg0 + b0) fp16
__device__ __align__(16) float  g_asrc[N_NODES * N_H];
__device__ __align__(16) float  g_adst[N_NODES * N_H];
__device__ __align__(16) uint32_t g_Bf[2 * HC * HC];   // frag-ordered tf32 W0|W1
__device__ int g_cnt[N_NODES];
__device__ int g_csr[N_NODES * MAXDEG];

// ---------------- helpers ----------------
__device__ __forceinline__ float lrelu(float x) { return x > 0.f ? x : NEG_SLOPE * x; }
__device__ __forceinline__ float eluf(float x)  { return x > 0.f ? x : expm1f(x); }
__device__ __forceinline__ float4 lrelu4(float4 a, float4 b) {
    float4 r;
    r.x = lrelu(a.x + b.x); r.y = lrelu(a.y + b.y);
    r.z = lrelu(a.z + b.z); r.w = lrelu(a.w + b.w);
    return r;
}
__device__ __forceinline__ float pick(float4 v, int h) {
    return h == 0 ? v.x : h == 1 ? v.y : h == 2 ? v.z : v.w;
}
__device__ __forceinline__ uint32_t tf32cvt(float f) {
    uint32_t r; asm("cvt.rna.tf32.f32 %0, %1;" : "=r"(r) : "f"(f)); return r;
}
__device__ __forceinline__ void mma_tf32(float4& c,
    uint32_t a0, uint32_t a1, uint32_t a2, uint32_t a3,
    uint32_t b0, uint32_t b1)
{
    asm volatile("mma.sync.aligned.m16n8k8.row.col.f32.tf32.tf32.f32 "
        "{%0,%1,%2,%3}, {%4,%5,%6,%7}, {%8,%9}, {%0,%1,%2,%3};"
        : "+f"(c.x), "+f"(c.y), "+f"(c.z), "+f"(c.w)
        : "r"(a0), "r"(a1), "r"(a2), "r"(a3), "r"(b0), "r"(b1));
}
__device__ __forceinline__ uint4 ldcg4u(const uint4* p) {
    uint4 v;
    asm("ld.global.cg.v4.u32 {%0,%1,%2,%3}, [%4];"
        : "=r"(v.x), "=r"(v.y), "=r"(v.z), "=r"(v.w) : "l"(p));
    return v;
}

// ---------------- merged init: zero counters + frag-order both W ----------------
__global__ void __launch_bounds__(256) init_misc(
    const float* __restrict__ W0, const float* __restrict__ W1)
{
    int i = blockIdx.x * 256 + threadIdx.x;
    if (i < N_NODES) g_cnt[i] = 0;
    if (i < HC * HC) {
        int j = i & 1, ln = (i >> 1) & 31, kt = i >> 6;
        int k = ((kt >> 4) << 3) + (ln & 3) + (j << 2);
        int n = ((kt & 15) << 3) + (ln >> 2);
        g_Bf[i] = tf32cvt(W0[k * HC + n]);
        g_Bf[HC * HC + i] = tf32cvt(W1[k * HC + n]);
    }
}

__global__ void __launch_bounds__(256) build_csr(const int* __restrict__ ei)
{
    int i = blockIdx.x * 256 + threadIdx.x;
    if (i >= N_EDGES) return;
    int src = ei[i], dst = ei[N_EDGES + i];
    int pos = atomicAdd(&g_cnt[dst], 1);
    if (pos < MAXDEG) g_csr[dst * MAXDEG + pos] = src;
}

// ---------------- tensor-core GEMM + fused alpha epilogue ----------------
__global__ void __launch_bounds__(256) gemm_tc(
    const float* __restrict__ X,
    const float* __restrict__ aw_src, const float* __restrict__ aw_dst,
    int layer)
{
    __shared__ uint32_t As[BM * AS_STRIDE];
    __shared__ float s_as[BM][N_H];
    __shared__ float s_ad[BM][N_H];

    int tid = threadIdx.x;
    int lane = tid & 31, warp = tid >> 5;
    int wr = warp & 3, wc = warp >> 2;
    int group = lane >> 2, tig = lane & 3;
    int brow = blockIdx.x * BM;

    // stage A tile as tf32 (layer1: fp16 pre-activated input)
    #pragma unroll
    for (int i = 0; i < 8; i++) {
        int idx4 = tid + i * 256;
        int row = idx4 >> 5, c4 = (idx4 & 31) << 2;
        float4 v = {0, 0, 0, 0};
        int grow = brow + row;
        if (grow < N_NODES) {
            if (layer) {
                uint2 hv = *(const uint2*)(g_aggh + grow * HC + c4);
                float2 a = __half22float2(*(const __half2*)&hv.x);
                float2 b = __half22float2(*(const __half2*)&hv.y);
                v = make_float4(a.x, a.y, b.x, b.y);
            } else {
                v = *(const float4*)(X + grow * HC + c4);
            }
        }
        uint32_t* dst = As + row * AS_STRIDE + c4;
        dst[0] = tf32cvt(v.x); dst[1] = tf32cvt(v.y);
        dst[2] = tf32cvt(v.z); dst[3] = tf32cvt(v.w);
    }
    __syncthreads();

    float4 C[8];
    #pragma unroll
    for (int nt = 0; nt < 8; nt++) C[nt] = make_float4(0.f, 0.f, 0.f, 0.f);

    const uint2* bp = (const uint2*)(g_Bf + layer * HC * HC) + (wc * 8) * 32 + lane;
    int ra = (wr * 16 + group) * AS_STRIDE;
    #pragma unroll
    for (int kk = 0; kk < 16; kk++) {
        const uint32_t* ap = As + kk * 8 + tig;
        uint32_t a0 = ap[ra];
        uint32_t a1 = ap[ra + 8 * AS_STRIDE];
        uint32_t a2 = ap[ra + 4];
        uint32_t a3 = ap[ra + 8 * AS_STRIDE + 4];
        const uint2* bpk = bp + kk * 16 * 32;
        uint2 b[8];
        #pragma unroll
        for (int nt = 0; nt < 8; nt++) b[nt] = bpk[nt * 32];
        #pragma unroll
        for (int nt = 0; nt < 8; nt++)
            mma_tf32(C[nt], a0, a1, a2, a3, b[nt].x, b[nt].y);
    }

    // ---- epilogue: fp16 feature store + fused alpha partials ----
    int row_a = brow + wr * 16 + group;
    int row_b = row_a + 8;
    float psa_lo = 0.f, psa_hi = 0.f, pda_lo = 0.f, pda_hi = 0.f;
    float psb_lo = 0.f, psb_hi = 0.f, pdb_lo = 0.f, pdb_hi = 0.f;
    #pragma unroll
    for (int nt = 0; nt < 8; nt++) {
        int col = wc * 64 + nt * 8 + tig * 2;
        if (row_a < N_NODES)
            *(__half2*)(g_xwh + row_a * HC + col) = __floats2half2_rn(C[nt].x, C[nt].y);
        if (row_b < N_NODES)
            *(__half2*)(g_xwh + row_b * HC + col) = __floats2half2_rn(C[nt].z, C[nt].w);
        float2 ws = *(const float2*)(aw_src + col);
        float2 wd = *(const float2*)(aw_dst + col);
        float sa = C[nt].x * ws.x + C[nt].y * ws.y;
        float da = C[nt].x * wd.x + C[nt].y * wd.y;
        float sb = C[nt].z * ws.x + C[nt].w * ws.y;
        float db = C[nt].z * wd.x + C[nt].w * wd.y;
        if (nt < 4) { psa_lo += sa; pda_lo += da; psb_lo += sb; pdb_lo += db; }
        else        { psa_hi += sa; pda_hi += da; psb_hi += sb; pdb_hi += db; }
    }
    #pragma unroll
    for (int o = 2; o >= 1; o >>= 1) {
        psa_lo += __shfl_xor_sync(0xffffffffu, psa_lo, o, 4);
        psa_hi += __shfl_xor_sync(0xffffffffu, psa_hi, o, 4);
        pda_lo += __shfl_xor_sync(0xffffffffu, pda_lo, o, 4);
        pda_hi += __shfl_xor_sync(0xffffffffu, pda_hi, o, 4);
        psb_lo += __shfl_xor_sync(0xffffffffu, psb_lo, o, 4);
        psb_hi += __shfl_xor_sync(0xffffffffu, psb_hi, o, 4);
        pdb_lo += __shfl_xor_sync(0xffffffffu, pdb_lo, o, 4);
        pdb_hi += __shfl_xor_sync(0xffffffffu, pdb_hi, o, 4);
    }
    if (tig == 0) {
        int rl_a = wr * 16 + group, rl_b = rl_a + 8;
        s_as[rl_a][wc * 2]     = psa_lo;
        s_as[rl_a][wc * 2 + 1] = psa_hi;
        s_ad[rl_a][wc * 2]     = pda_lo;
        s_ad[rl_a][wc * 2 + 1] = pda_hi;
        s_as[rl_b][wc * 2]     = psb_lo;
        s_as[rl_b][wc * 2 + 1] = psb_hi;
        s_ad[rl_b][wc * 2]     = pdb_lo;
        s_ad[rl_b][wc * 2 + 1] = pdb_hi;
    }
    __syncthreads();
    {
        int row = tid >> 2, h = tid & 3;
        int grow = brow + row;
        if (grow < N_NODES) {
            g_asrc[grow * N_H + h] = s_as[row][h];
            g_adst[grow * N_H + h] = s_ad[row][h];
        }
    }
}

// ---------------- fused softmax + aggregation (warp per dst) ----------------
// Phase A: 32 lanes own edges -> logits, warp max/denominator.
// Phase B: 2 edges per warp; 16 lanes x LDG.128 cover one 256B fp16 row.
// FINAL=0: fuses elu(acc + b0), stores fp16 layer-1 input.
// FINAL=1: fuses regression head.
template <int FINAL>
__global__ void __launch_bounds__(256) attn_agg(
    const float* __restrict__ bias, const float* __restrict__ Wr,
    const float* __restrict__ br, float* __restrict__ out)
{
    __shared__ float4 s_w[8][MAXDEG];
    __shared__ int    s_src[8][MAXDEG];

    int t = blockIdx.x * 256 + threadIdx.x;
    int row = t >> 5, lane = t & 31, warp = threadIdx.x >> 5;
    if (row >= N_NODES) return;

    float4 ad = ((const float4*)g_adst)[row];
    float4 asf = ((const float4*)g_asrc)[row];
    float4 lself = lrelu4(asf, ad);
    int cnt = min(g_cnt[row], MAXDEG);

    // ---- phase A ----
    float4 l0, l1, l2;
    int s0 = 0, s1 = 0, s2 = 0;
    float4 m = lself;
    {
        int j = lane;
        if (j < cnt) {
            s0 = g_csr[row * MAXDEG + j];
            l0 = lrelu4(((const float4*)g_asrc)[s0], ad);
            m.x = fmaxf(m.x, l0.x); m.y = fmaxf(m.y, l0.y);
            m.z = fmaxf(m.z, l0.z); m.w = fmaxf(m.w, l0.w);
        }
        j += 32;
        if (j < cnt) {
            s1 = g_csr[row * MAXDEG + j];
            l1 = lrelu4(((const float4*)g_asrc)[s1], ad);
            m.x = fmaxf(m.x, l1.x); m.y = fmaxf(m.y, l1.y);
            m.z = fmaxf(m.z, l1.z); m.w = fmaxf(m.w, l1.w);
        }
        j += 32;
        if (j < cnt) {
            s2 = g_csr[row * MAXDEG + j];
            l2 = lrelu4(((const float4*)g_asrc)[s2], ad);
            m.x = fmaxf(m.x, l2.x); m.y = fmaxf(m.y, l2.y);
            m.z = fmaxf(m.z, l2.z); m.w = fmaxf(m.w, l2.w);
        }
    }
    #pragma unroll
    for (int o = 16; o >= 1; o >>= 1) {
        m.x = fmaxf(m.x, __shfl_xor_sync(0xffffffffu, m.x, o));
        m.y = fmaxf(m.y, __shfl_xor_sync(0xffffffffu, m.y, o));
        m.z = fmaxf(m.z, __shfl_xor_sync(0xffffffffu, m.z, o));
        m.w = fmaxf(m.w, __shfl_xor_sync(0xffffffffu, m.w, o));
    }

    float4 den = {0, 0, 0, 0};
    {
        int j = lane;
        if (j < cnt) {
            float4 w;
            w.x = __expf(l0.x - m.x); w.y = __expf(l0.y - m.y);
            w.z = __expf(l0.z - m.z); w.w = __expf(l0.w - m.w);
            den.x += w.x; den.y += w.y; den.z += w.z; den.w += w.w;
            s_w[warp][j] = w; s_src[warp][j] = s0;
        }
        j += 32;
        if (j < cnt) {
            float4 w;
            w.x = __expf(l1.x - m.x); w.y = __expf(l1.y - m.y);
            w.z = __expf(l1.z - m.z); w.w = __expf(l1.w - m.w);
            den.x += w.x; den.y += w.y; den.z += w.z; den.w += w.w;
            s_w[warp][j] = w; s_src[warp][j] = s1;
        }
        j += 32;
        if (j < cnt) {
            float4 w;
            w.x = __expf(l2.x - m.x); w.y = __expf(l2.y - m.y);
            w.z = __expf(l2.z - m.z); w.w = __expf(l2.w - m.w);
            den.x += w.x; den.y += w.y; den.z += w.z; den.w += w.w;
            s_w[warp][j] = w; s_src[warp][j] = s2;
        }
    }
    #pragma unroll
    for (int o = 16; o >= 1; o >>= 1) {
        den.x += __shfl_xor_sync(0xffffffffu, den.x, o);
        den.y += __shfl_xor_sync(0xffffffffu, den.y, o);
        den.z += __shfl_xor_sync(0xffffffffu, den.z, o);
        den.w += __shfl_xor_sync(0xffffffffu, den.w, o);
    }
    float4 wself;
    wself.x = __expf(lself.x - m.x); wself.y = __expf(lself.y - m.y);
    wself.z = __expf(lself.z - m.z); wself.w = __expf(lself.w - m.w);
    den.x += wself.x; den.y += wself.y; den.z += wself.z; den.w += wself.w;
    __syncwarp();

    // ---- phase B: 2 edges/warp, LDG.128/lane ----
    int half_id = lane >> 4;
    int l16 = lane & 15;
    int h = l16 >> 2;
    const uint4* xwh = (const uint4*)g_xwh;   // 16 uint4 per row
    const float* wp = (const float*)&s_w[warp][0];
    float acc[8] = {0, 0, 0, 0, 0, 0, 0, 0};

    if (half_id == 0) {
        uint4 rv = xwh[row * 16 + l16];
        float w = pick(wself, h);
        float2 f0 = __half22float2(*(const __half2*)&rv.x);
        float2 f1 = __half22float2(*(const __half2*)&rv.y);
        float2 f2 = __half22float2(*(const __half2*)&rv.z);
        float2 f3 = __half22float2(*(const __half2*)&rv.w);
        acc[0] = w * f0.x; acc[1] = w * f0.y; acc[2] = w * f1.x; acc[3] = w * f1.y;
        acc[4] = w * f2.x; acc[5] = w * f2.y; acc[6] = w * f3.x; acc[7] = w * f3.y;
    }
    for (int i = half_id; i < cnt; i += 2) {
        int s = s_src[warp][i];
        float w = wp[i * 4 + h];
        uint4 rv = ldcg4u(xwh + s * 16 + l16);
        float2 f0 = __half22float2(*(const __half2*)&rv.x);
        float2 f1 = __half22float2(*(const __half2*)&rv.y);
        float2 f2 = __half22float2(*(const __half2*)&rv.z);
        float2 f3 = __half22float2(*(const __half2*)&rv.w);
        acc[0] += w * f0.x; acc[1] += w * f0.y; acc[2] += w * f1.x; acc[3] += w * f1.y;
        acc[4] += w * f2.x; acc[5] += w * f2.y; acc[6] += w * f3.x; acc[7] += w * f3.y;
    }
    #pragma unroll
    for (int k = 0; k < 8; k++)
        acc[k] += __shfl_down_sync(0xffffffffu, acc[k], 16);

    if (half_id == 0) {
        float r = 1.0f / pick(den, h);
        int c0 = l16 * 8;
        if (FINAL == 0) {
            // fused: elu(acc + b0) -> fp16 layer-1 input
            float4 ba = *(const float4*)(bias + c0);
            float4 bbq = *(const float4*)(bias + c0 + 4);
            __half2 o0 = __floats2half2_rn(eluf(acc[0]*r + ba.x), eluf(acc[1]*r + ba.y));
            __half2 o1 = __floats2half2_rn(eluf(acc[2]*r + ba.z), eluf(acc[3]*r + ba.w));
            __half2 o2 = __floats2half2_rn(eluf(acc[4]*r + bbq.x), eluf(acc[5]*r + bbq.y));
            __half2 o3 = __floats2half2_rn(eluf(acc[6]*r + bbq.z), eluf(acc[7]*r + bbq.w));
            uint4 pk;
            pk.x = *(const uint32_t*)&o0; pk.y = *(const uint32_t*)&o1;
            pk.z = *(const uint32_t*)&o2; pk.w = *(const uint32_t*)&o3;
            ((uint4*)g_aggh)[row * 16 + l16] = pk;
        } else {
            float4 ba = *(const float4*)(bias + c0);
            float4 bbq = *(const float4*)(bias + c0 + 4);
            float4 w0 = *(const float4*)(Wr + c0);
            float4 w1 = *(const float4*)(Wr + c0 + 4);
            float p = eluf(acc[0]*r + ba.x) * w0.x + eluf(acc[1]*r + ba.y) * w0.y
                    + eluf(acc[2]*r + ba.z) * w0.z + eluf(acc[3]*r + ba.w) * w0.w
                    + eluf(acc[4]*r + bbq.x) * w1.x + eluf(acc[5]*r + bbq.y) * w1.y
                    + eluf(acc[6]*r + bbq.z) * w1.z + eluf(acc[7]*r + bbq.w) * w1.w;
            #pragma unroll
            for (int o = 8; o >= 1; o >>= 1)
                p += __shfl_xor_sync(0xffffffffu, p, o, 16);
            if (l16 == 0) out[row] = p + br[0];
        }
    }
}

// ---------------- launch ----------------
extern "C" void kernel_launch(void* const* d_in, const int* in_sizes, int n_in,
                              void* d_out, int out_size)
{
    const float* x   = (const float*)d_in[0];
    const int*   ei  = (const int*)  d_in[1];
    const float* W0  = (const float*)d_in[2];
    const float* as0 = (const float*)d_in[3];
    const float* ad0 = (const float*)d_in[4];
    const float* b0  = (const float*)d_in[5];
    const float* W1  = (const float*)d_in[6];
    const float* as1 = (const float*)d_in[7];
    const float* ad1 = (const float*)d_in[8];
    const float* b1  = (const float*)d_in[9];
    const float* Wr  = (const float*)d_in[10];
    const float* br  = (const float*)d_in[11];
    float* out = (float*)d_out;

    const int IB = (N_NODES + 255) / 256;     // covers both N_NODES and HC*HC
    const int HB = (N_EDGES + 255) / 256;
    const int TB = (N_NODES + BM - 1) / BM;
    const int AB = (N_NODES + 7) / 8;

    init_misc<<<IB, 256>>>(W0, W1);
    build_csr<<<HB, 256>>>(ei);

    gemm_tc<<<TB, 256>>>(x, as0, ad0, 0);
    attn_agg<0><<<AB, 256>>>(b0, Wr, br, out);

    gemm_tc<<<TB, 256>>>(x, as1, ad1, 1);
    attn_agg<1><<<AB, 256>>>(b1, Wr, br, out);
}

// round 8
// speedup vs baseline: 1.1239x; 1.1239x over previous
#include <cuda_runtime.h>
#include <cuda_fp16.h>
#include <math.h>
#include <stdint.h>

#define N_NODES 50000
#define N_EDGES 800000
#define N_H 4
#define HC 128
#define NEG_SLOPE 0.2f
#define MAXDEG 96

#define BM 64
#define AS_STRIDE 132   // padded row stride (uint32) for A tile

// ---------------- scratch (device globals; no allocation) ----------------
__device__ __align__(16) __half g_xwh[N_NODES * HC];   // A @ W (fp16 features)
__device__ __align__(16) __half g_aggh[N_NODES * HC];  // elu(agg0 + b0) fp16
__device__ __align__(16) float  g_asrc[N_NODES * N_H];
__device__ __align__(16) float  g_adst[N_NODES * N_H];
__device__ __align__(16) uint32_t g_Bf[2 * HC * HC];   // frag-ordered tf32 W0|W1
__device__ int g_cnt[N_NODES];
__device__ int g_csr[N_NODES * MAXDEG];

// ---------------- helpers ----------------
__device__ __forceinline__ float lrelu(float x) { return x > 0.f ? x : NEG_SLOPE * x; }
__device__ __forceinline__ float eluf(float x)  { return x > 0.f ? x : expm1f(x); }
__device__ __forceinline__ float4 lrelu4(float4 a, float4 b) {
    float4 r;
    r.x = lrelu(a.x + b.x); r.y = lrelu(a.y + b.y);
    r.z = lrelu(a.z + b.z); r.w = lrelu(a.w + b.w);
    return r;
}
__device__ __forceinline__ float pick(float4 v, int h) {
    return h == 0 ? v.x : h == 1 ? v.y : h == 2 ? v.z : v.w;
}
__device__ __forceinline__ uint32_t tf32cvt(float f) {
    uint32_t r; asm("cvt.rna.tf32.f32 %0, %1;" : "=r"(r) : "f"(f)); return r;
}
__device__ __forceinline__ void mma_tf32(float4& c,
    uint32_t a0, uint32_t a1, uint32_t a2, uint32_t a3,
    uint32_t b0, uint32_t b1)
{
    asm volatile("mma.sync.aligned.m16n8k8.row.col.f32.tf32.tf32.f32 "
        "{%0,%1,%2,%3}, {%4,%5,%6,%7}, {%8,%9}, {%0,%1,%2,%3};"
        : "+f"(c.x), "+f"(c.y), "+f"(c.z), "+f"(c.w)
        : "r"(a0), "r"(a1), "r"(a2), "r"(a3), "r"(b0), "r"(b1));
}
__device__ __forceinline__ uint2 ldcg2(const uint2* p) {
    uint2 v;
    asm("ld.global.cg.v2.u32 {%0,%1}, [%2];" : "=r"(v.x), "=r"(v.y) : "l"(p));
    return v;
}

// ---------------- merged init: zero counters + frag-order both W ----------------
__global__ void __launch_bounds__(256) init_misc(
    const float* __restrict__ W0, const float* __restrict__ W1)
{
    int i = blockIdx.x * 256 + threadIdx.x;
    if (i < N_NODES) g_cnt[i] = 0;
    if (i < HC * HC) {
        int j = i & 1, ln = (i >> 1) & 31, kt = i >> 6;
        int k = ((kt >> 4) << 3) + (ln & 3) + (j << 2);
        int n = ((kt & 15) << 3) + (ln >> 2);
        g_Bf[i] = tf32cvt(W0[k * HC + n]);
        g_Bf[HC * HC + i] = tf32cvt(W1[k * HC + n]);
    }
}

__global__ void __launch_bounds__(256) build_csr(const int* __restrict__ ei)
{
    int i = blockIdx.x * 256 + threadIdx.x;
    if (i >= N_EDGES) return;
    int src = ei[i], dst = ei[N_EDGES + i];
    int pos = atomicAdd(&g_cnt[dst], 1);
    if (pos < MAXDEG) g_csr[dst * MAXDEG + pos] = src;
}

// ---------------- tensor-core GEMM + fused alpha epilogue ----------------
__global__ void __launch_bounds__(256) gemm_tc(
    const float* __restrict__ X,
    const float* __restrict__ aw_src, const float* __restrict__ aw_dst,
    int layer)
{
    __shared__ uint32_t As[BM * AS_STRIDE];
    __shared__ float s_as[BM][N_H];
    __shared__ float s_ad[BM][N_H];

    int tid = threadIdx.x;
    int lane = tid & 31, warp = tid >> 5;
    int wr = warp & 3, wc = warp >> 2;
    int group = lane >> 2, tig = lane & 3;
    int brow = blockIdx.x * BM;

    // stage A tile as tf32 (layer1: fp16 pre-activated input)
    #pragma unroll
    for (int i = 0; i < 8; i++) {
        int idx4 = tid + i * 256;
        int row = idx4 >> 5, c4 = (idx4 & 31) << 2;
        float4 v = {0, 0, 0, 0};
        int grow = brow + row;
        if (grow < N_NODES) {
            if (layer) {
                uint2 hv = *(const uint2*)(g_aggh + grow * HC + c4);
                float2 a = __half22float2(*(const __half2*)&hv.x);
                float2 b = __half22float2(*(const __half2*)&hv.y);
                v = make_float4(a.x, a.y, b.x, b.y);
            } else {
                v = *(const float4*)(X + grow * HC + c4);
            }
        }
        uint32_t* dst = As + row * AS_STRIDE + c4;
        dst[0] = tf32cvt(v.x); dst[1] = tf32cvt(v.y);
        dst[2] = tf32cvt(v.z); dst[3] = tf32cvt(v.w);
    }
    __syncthreads();

    float4 C[8];
    #pragma unroll
    for (int nt = 0; nt < 8; nt++) C[nt] = make_float4(0.f, 0.f, 0.f, 0.f);

    const uint2* bp = (const uint2*)(g_Bf + layer * HC * HC) + (wc * 8) * 32 + lane;
    int ra = (wr * 16 + group) * AS_STRIDE;
    #pragma unroll
    for (int kk = 0; kk < 16; kk++) {
        const uint32_t* ap = As + kk * 8 + tig;
        uint32_t a0 = ap[ra];
        uint32_t a1 = ap[ra + 8 * AS_STRIDE];
        uint32_t a2 = ap[ra + 4];
        uint32_t a3 = ap[ra + 8 * AS_STRIDE + 4];
        const uint2* bpk = bp + kk * 16 * 32;
        uint2 b[8];
        #pragma unroll
        for (int nt = 0; nt < 8; nt++) b[nt] = bpk[nt * 32];
        #pragma unroll
        for (int nt = 0; nt < 8; nt++)
            mma_tf32(C[nt], a0, a1, a2, a3, b[nt].x, b[nt].y);
    }

    // ---- epilogue: fp16 feature store + fused alpha partials ----
    int row_a = brow + wr * 16 + group;
    int row_b = row_a + 8;
    float psa_lo = 0.f, psa_hi = 0.f, pda_lo = 0.f, pda_hi = 0.f;
    float psb_lo = 0.f, psb_hi = 0.f, pdb_lo = 0.f, pdb_hi = 0.f;
    #pragma unroll
    for (int nt = 0; nt < 8; nt++) {
        int col = wc * 64 + nt * 8 + tig * 2;
        if (row_a < N_NODES)
            *(__half2*)(g_xwh + row_a * HC + col) = __floats2half2_rn(C[nt].x, C[nt].y);
        if (row_b < N_NODES)
            *(__half2*)(g_xwh + row_b * HC + col) = __floats2half2_rn(C[nt].z, C[nt].w);
        float2 ws = *(const float2*)(aw_src + col);
        float2 wd = *(const float2*)(aw_dst + col);
        float sa = C[nt].x * ws.x + C[nt].y * ws.y;
        float da = C[nt].x * wd.x + C[nt].y * wd.y;
        float sb = C[nt].z * ws.x + C[nt].w * ws.y;
        float db = C[nt].z * wd.x + C[nt].w * wd.y;
        if (nt < 4) { psa_lo += sa; pda_lo += da; psb_lo += sb; pdb_lo += db; }
        else        { psa_hi += sa; pda_hi += da; psb_hi += sb; pdb_hi += db; }
    }
    #pragma unroll
    for (int o = 2; o >= 1; o >>= 1) {
        psa_lo += __shfl_xor_sync(0xffffffffu, psa_lo, o, 4);
        psa_hi += __shfl_xor_sync(0xffffffffu, psa_hi, o, 4);
        pda_lo += __shfl_xor_sync(0xffffffffu, pda_lo, o, 4);
        pda_hi += __shfl_xor_sync(0xffffffffu, pda_hi, o, 4);
        psb_lo += __shfl_xor_sync(0xffffffffu, psb_lo, o, 4);
        psb_hi += __shfl_xor_sync(0xffffffffu, psb_hi, o, 4);
        pdb_lo += __shfl_xor_sync(0xffffffffu, pdb_lo, o, 4);
        pdb_hi += __shfl_xor_sync(0xffffffffu, pdb_hi, o, 4);
    }
    if (tig == 0) {
        int rl_a = wr * 16 + group, rl_b = rl_a + 8;
        s_as[rl_a][wc * 2]     = psa_lo;
        s_as[rl_a][wc * 2 + 1] = psa_hi;
        s_ad[rl_a][wc * 2]     = pda_lo;
        s_ad[rl_a][wc * 2 + 1] = pda_hi;
        s_as[rl_b][wc * 2]     = psb_lo;
        s_as[rl_b][wc * 2 + 1] = psb_hi;
        s_ad[rl_b][wc * 2]     = pdb_lo;
        s_ad[rl_b][wc * 2 + 1] = pdb_hi;
    }
    __syncthreads();
    {
        int row = tid >> 2, h = tid & 3;
        int grow = brow + row;
        if (grow < N_NODES) {
            g_asrc[grow * N_H + h] = s_as[row][h];
            g_adst[grow * N_H + h] = s_ad[row][h];
        }
    }
}

// ---------------- fused softmax + aggregation (warp per dst) ----------------
// Phase A: 32 lanes own edges -> logits, warp max/denominator.
// Phase B (R6 pattern): 32 lanes x uint2 (8B) per edge, unit-stride unrolled.
// FINAL=0: fuses elu(acc + b0) -> fp16 layer-1 input.
// FINAL=1: fuses regression head.
template <int FINAL>
__global__ void __launch_bounds__(256) attn_agg(
    const float* __restrict__ bias, const float* __restrict__ Wr,
    const float* __restrict__ br, float* __restrict__ out)
{
    __shared__ float4 s_w[8][MAXDEG];
    __shared__ int    s_src[8][MAXDEG];

    int t = blockIdx.x * 256 + threadIdx.x;
    int row = t >> 5, lane = t & 31, warp = threadIdx.x >> 5;
    if (row >= N_NODES) return;
    int h = lane >> 3;

    float4 ad = ((const float4*)g_adst)[row];
    float4 asf = ((const float4*)g_asrc)[row];
    float4 lself = lrelu4(asf, ad);
    int cnt = min(g_cnt[row], MAXDEG);

    // ---- phase A ----
    float4 l0, l1, l2;
    int s0 = 0, s1 = 0, s2 = 0;
    float4 m = lself;
    {
        int j = lane;
        if (j < cnt) {
            s0 = g_csr[row * MAXDEG + j];
            l0 = lrelu4(((const float4*)g_asrc)[s0], ad);
            m.x = fmaxf(m.x, l0.x); m.y = fmaxf(m.y, l0.y);
            m.z = fmaxf(m.z, l0.z); m.w = fmaxf(m.w, l0.w);
        }
        j += 32;
        if (j < cnt) {
            s1 = g_csr[row * MAXDEG + j];
            l1 = lrelu4(((const float4*)g_asrc)[s1], ad);
            m.x = fmaxf(m.x, l1.x); m.y = fmaxf(m.y, l1.y);
            m.z = fmaxf(m.z, l1.z); m.w = fmaxf(m.w, l1.w);
        }
        j += 32;
        if (j < cnt) {
            s2 = g_csr[row * MAXDEG + j];
            l2 = lrelu4(((const float4*)g_asrc)[s2], ad);
            m.x = fmaxf(m.x, l2.x); m.y = fmaxf(m.y, l2.y);
            m.z = fmaxf(m.z, l2.z); m.w = fmaxf(m.w, l2.w);
        }
    }
    #pragma unroll
    for (int o = 16; o >= 1; o >>= 1) {
        m.x = fmaxf(m.x, __shfl_xor_sync(0xffffffffu, m.x, o));
        m.y = fmaxf(m.y, __shfl_xor_sync(0xffffffffu, m.y, o));
        m.z = fmaxf(m.z, __shfl_xor_sync(0xffffffffu, m.z, o));
        m.w = fmaxf(m.w, __shfl_xor_sync(0xffffffffu, m.w, o));
    }

    float4 den = {0, 0, 0, 0};
    {
        int j = lane;
        if (j < cnt) {
            float4 w;
            w.x = __expf(l0.x - m.x); w.y = __expf(l0.y - m.y);
            w.z = __expf(l0.z - m.z); w.w = __expf(l0.w - m.w);
            den.x += w.x; den.y += w.y; den.z += w.z; den.w += w.w;
            s_w[warp][j] = w; s_src[warp][j] = s0;
        }
        j += 32;
        if (j < cnt) {
            float4 w;
            w.x = __expf(l1.x - m.x); w.y = __expf(l1.y - m.y);
            w.z = __expf(l1.z - m.z); w.w = __expf(l1.w - m.w);
            den.x += w.x; den.y += w.y; den.z += w.z; den.w += w.w;
            s_w[warp][j] = w; s_src[warp][j] = s1;
        }
        j += 32;
        if (j < cnt) {
            float4 w;
            w.x = __expf(l2.x - m.x); w.y = __expf(l2.y - m.y);
            w.z = __expf(l2.z - m.z); w.w = __expf(l2.w - m.w);
            den.x += w.x; den.y += w.y; den.z += w.z; den.w += w.w;
            s_w[warp][j] = w; s_src[warp][j] = s2;
        }
    }
    #pragma unroll
    for (int o = 16; o >= 1; o >>= 1) {
        den.x += __shfl_xor_sync(0xffffffffu, den.x, o);
        den.y += __shfl_xor_sync(0xffffffffu, den.y, o);
        den.z += __shfl_xor_sync(0xffffffffu, den.z, o);
        den.w += __shfl_xor_sync(0xffffffffu, den.w, o);
    }
    float4 wself;
    wself.x = __expf(lself.x - m.x); wself.y = __expf(lself.y - m.y);
    wself.z = __expf(lself.z - m.z); wself.w = __expf(lself.w - m.w);
    den.x += wself.x; den.y += wself.y; den.z += wself.z; den.w += wself.w;
    __syncwarp();

    // ---- phase B: fp16 gather, 8B per lane per edge (R6 pattern) ----
    const uint2* xwh = (const uint2*)g_xwh;   // 32 uint2 per row
    uint2 rs = xwh[row * 32 + lane];
    float2 f0 = __half22float2(*(const __half2*)&rs.x);
    float2 f1 = __half22float2(*(const __half2*)&rs.y);
    float w0 = pick(wself, h);
    float4 acc = {w0 * f0.x, w0 * f0.y, w0 * f1.x, w0 * f1.y};
    const float* wp = (const float*)&s_w[warp][0];
    #pragma unroll 4
    for (int i = 0; i < cnt; i++) {
        int s = s_src[warp][i];
        float w = wp[i * 4 + h];
        uint2 rv = ldcg2(xwh + s * 32 + lane);
        float2 g0 = __half22float2(*(const __half2*)&rv.x);
        float2 g1 = __half22float2(*(const __half2*)&rv.y);
        acc.x += w * g0.x; acc.y += w * g0.y;
        acc.z += w * g1.x; acc.w += w * g1.y;
    }
    float r = 1.0f / pick(den, h);
    acc.x *= r; acc.y *= r; acc.z *= r; acc.w *= r;

    int c0 = lane * 4;
    if (FINAL == 0) {
        // fused: elu(acc + b0) -> fp16 layer-1 input
        float4 ba = *(const float4*)(bias + c0);
        __half2 o0 = __floats2half2_rn(eluf(acc.x + ba.x), eluf(acc.y + ba.y));
        __half2 o1 = __floats2half2_rn(eluf(acc.z + ba.z), eluf(acc.w + ba.w));
        uint2 pk;
        pk.x = *(const uint32_t*)&o0; pk.y = *(const uint32_t*)&o1;
        ((uint2*)g_aggh)[row * 32 + lane] = pk;
    } else {
        float4 ba = *(const float4*)(bias + c0);
        float4 wr = *(const float4*)(Wr + c0);
        float p = eluf(acc.x + ba.x) * wr.x + eluf(acc.y + ba.y) * wr.y
                + eluf(acc.z + ba.z) * wr.z + eluf(acc.w + ba.w) * wr.w;
        #pragma unroll
        for (int o = 16; o >= 1; o >>= 1) p += __shfl_xor_sync(0xffffffffu, p, o);
        if (lane == 0) out[row] = p + br[0];
    }
}

// ---------------- launch ----------------
extern "C" void kernel_launch(void* const* d_in, const int* in_sizes, int n_in,
                              void* d_out, int out_size)
{
    const float* x   = (const float*)d_in[0];
    const int*   ei  = (const int*)  d_in[1];
    const float* W0  = (const float*)d_in[2];
    const float* as0 = (const float*)d_in[3];
    const float* ad0 = (const float*)d_in[4];
    const float* b0  = (const float*)d_in[5];
    const float* W1  = (const float*)d_in[6];
    const float* as1 = (const float*)d_in[7];
    const float* ad1 = (const float*)d_in[8];
    const float* b1  = (const float*)d_in[9];
    const float* Wr  = (const float*)d_in[10];
    const float* br  = (const float*)d_in[11];
    float* out = (float*)d_out;

    const int IB = (N_NODES + 255) / 256;
    const int HB = (N_EDGES + 255) / 256;
    const int TB = (N_NODES + BM - 1) / BM;
    const int AB = (N_NODES + 7) / 8;

    init_misc<<<IB, 256>>>(W0, W1);
    build_csr<<<HB, 256>>>(ei);

    gemm_tc<<<TB, 256>>>(x, as0, ad0, 0);
    attn_agg<0><<<AB, 256>>>(b0, Wr, br, out);

    gemm_tc<<<TB, 256>>>(x, as1, ad1, 1);
    attn_agg<1><<<AB, 256>>>(b1, Wr, br, out);
}